// round 2
// baseline (speedup 1.0000x reference)
#include <cuda_runtime.h>
#include <math.h>

#define NSAMP   4194304
#define HOP     128
#define NFFT    512
#define NH      256          // complex FFT size (real-packing trick)
#define NFRAMES 32769
#define NBINS   257
#define OUT_STRIDE (3*NBINS) // 771
#define FPB     4            // frames per block
#define PI_F 3.14159265358979323846f

// Scratch (no cudaMalloc allowed)
__device__ float2 g_partial[512];
__device__ float  g_c;

// ---------------------------------------------------------------------------
// Pass 1: 512 blocks x 256 threads, exactly 8 independent float4 loads each
// ---------------------------------------------------------------------------
__global__ __launch_bounds__(256) void reduce_pass1(const float* __restrict__ x) {
    __shared__ float s_sum[256];
    __shared__ float s_sq[256];
    const int tid = threadIdx.x;
    const float4* x4 = (const float4*)x;
    const int gt = blockIdx.x * 256 + tid;          // 0 .. 131071
    float sum = 0.f, sq = 0.f;
    #pragma unroll
    for (int k = 0; k < 8; ++k) {
        float4 v = x4[gt + k * 131072];
        sum += (v.x + v.y) + (v.z + v.w);
        sq  += (v.x*v.x + v.y*v.y) + (v.z*v.z + v.w*v.w);
    }
    s_sum[tid] = sum; s_sq[tid] = sq;
    __syncthreads();
    for (int s = 128; s > 0; s >>= 1) {
        if (tid < s) { s_sum[tid] += s_sum[tid + s]; s_sq[tid] += s_sq[tid + s]; }
        __syncthreads();
    }
    if (tid == 0) g_partial[blockIdx.x] = make_float2(s_sum[0], s_sq[0]);
}

// ---------------------------------------------------------------------------
// Pass 2: final combine in double, c = mean / std (ddof=1)
// ---------------------------------------------------------------------------
__global__ __launch_bounds__(256) void reduce_pass2() {
    __shared__ double s_sum[256];
    __shared__ double s_sq[256];
    const int tid = threadIdx.x;
    float2 p0 = g_partial[tid];
    float2 p1 = g_partial[tid + 256];
    s_sum[tid] = (double)p0.x + (double)p1.x;
    s_sq[tid]  = (double)p0.y + (double)p1.y;
    __syncthreads();
    for (int s = 128; s > 0; s >>= 1) {
        if (tid < s) { s_sum[tid] += s_sum[tid + s]; s_sq[tid] += s_sq[tid + s]; }
        __syncthreads();
    }
    if (tid == 0) {
        double S = s_sum[0], SS = s_sq[0];
        double mean = S / (double)NSAMP;
        double var  = (SS - S * S / (double)NSAMP) / (double)(NSAMP - 1);
        g_c = (float)(mean / sqrt(var));
    }
}

__device__ __forceinline__ float2 cmul(float2 a, float2 b) {
    return make_float2(a.x * b.x - a.y * b.y, a.x * b.y + a.y * b.x);
}
__device__ __forceinline__ float2 cadd(float2 a, float2 b) { return make_float2(a.x + b.x, a.y + b.y); }
__device__ __forceinline__ float2 csub(float2 a, float2 b) { return make_float2(a.x - b.x, a.y - b.y); }

// ---------------------------------------------------------------------------
// Per-bin epilogue: log-magnitude, sin(phase), cos(phase)
// sin(unwrap(phase)) == sin(phase) (unwrap adds exact multiples of 2*pi)
// ---------------------------------------------------------------------------
__device__ __forceinline__ void emit_bin(const float2* __restrict__ Z,
                                         const float2* __restrict__ tw,
                                         float* __restrict__ orow, int k) {
    float2 zk = Z[k & (NH - 1)];
    float2 zc = Z[(NH - k) & (NH - 1)];
    // Xe = (Zk + conj(Zc))/2 ; Xo = -i*(Zk - conj(Zc))/2
    float xer = 0.5f * (zk.x + zc.x);
    float xei = 0.5f * (zk.y - zc.y);
    float xox = 0.5f * (zk.y + zc.y);
    float xoy = -0.5f * (zk.x - zc.x);
    float2 w = tw[k];                   // e^{-i*pi*k/256}
    float cw = w.x, sw = w.y;
    float re = xer + cw * xox - sw * xoy;
    float im = xei + cw * xoy + sw * xox;

    float r2 = re * re + im * im;
    float lm, sv, cv;
    if (r2 > 0.f) {
        float inv = rsqrtf(r2);
        float mag = r2 * inv;
        lm = __logf(mag + 1e-9f);
        sv = im * inv;
        cv = re * inv;
    } else {
        lm = __logf(1e-9f);
        sv = 0.f;
        cv = 1.f;
    }
    orow[k]             = lm;
    orow[NBINS + k]     = sv;
    orow[2 * NBINS + k] = cv;
}

// ---------------------------------------------------------------------------
// STFT: 4 frames per 256-thread block, 64 threads per frame.
// Real input packed into 256-pt complex FFT: radix-4 Stockham, 4 stages.
// Twiddles + Hann window + epilogue rotations all from one shared table.
// ---------------------------------------------------------------------------
__global__ __launch_bounds__(256) void stft_kernel(const float* __restrict__ audio,
                                                   float* __restrict__ out) {
    __shared__ float2 tw[NBINS];          // tw[k] = e^{-i*pi*k/256}, k=0..256
    __shared__ float2 bufA[FPB][NH];
    __shared__ float2 bufB[FPB][NH];

    const int tid = threadIdx.x;
    const int fid = tid >> 6;             // frame within block
    const int u   = tid & 63;             // thread within frame
    const int t   = blockIdx.x * FPB + fid;
    const bool valid = (t < NFRAMES);
    const float c = g_c;

    // Build twiddle table: tw[k] = (cos(pi k/256), -sin(pi k/256))
    if (tid < 256) {
        float s, co;
        sincospif((float)tid * (1.f / 256.f), &s, &co);
        tw[tid] = make_float2(co, -s);
    }
    if (tid == 0) tw[256] = make_float2(-1.f, 0.f);
    __syncthreads();

    // Load + reflect + normalize + Hann; pack z[n] = x[2n] + i*x[2n+1]
    // Thread u owns points n = u + 64r, r = 0..3.
    const int base = t * HOP - NFFT / 2;
    {
        #pragma unroll
        for (int r = 0; r < 4; ++r) {
            int n  = u + 64 * r;
            int j0 = 2 * n;
            float v0, v1;
            if (valid && base >= 0 && base + NFFT <= NSAMP) {
                float2 v = *(const float2*)(audio + base + j0);
                v0 = v.x - c; v1 = v.y - c;
            } else if (valid) {
                int p0 = base + j0, p1 = p0 + 1;
                if (p0 < 0) p0 = -p0; else if (p0 >= NSAMP) p0 = 2 * NSAMP - 2 - p0;
                if (p1 < 0) p1 = -p1; else if (p1 >= NSAMP) p1 = 2 * NSAMP - 2 - p1;
                v0 = audio[p0] - c; v1 = audio[p1] - c;
            } else {
                v0 = 0.f; v1 = 0.f;
            }
            // hann[j] = 0.5*(1 - cos(pi*j/256)) ; cos from table (symmetric)
            int j1 = j0 + 1;
            int jm0 = (j0 <= 256) ? j0 : 512 - j0;
            int jm1 = (j1 <= 256) ? j1 : 512 - j1;
            float h0 = 0.5f * (1.f - tw[jm0].x);
            float h1 = 0.5f * (1.f - tw[jm1].x);
            bufA[fid][n] = make_float2(v0 * h0, v1 * h1);
        }
    }
    __syncthreads();

    // 4 fused radix-4 Stockham stages (pairs of radix-2 stages s, s+1)
    float2* src = bufA[fid];
    float2* dst = bufB[fid];
    #pragma unroll
    for (int s = 0; s < 8; s += 2) {
        const int Nsz = 1 << s;
        const int k = u & (Nsz - 1);
        float2 a  = src[u];
        float2 b  = src[u + 64];
        float2 c2 = src[u + 128];
        float2 d2 = src[u + 192];

        float2 y0, y1, y2, y3, wy2, wy3;
        if (s == 0) {
            // k == 0: all twiddles are 1
            y0 = cadd(a, c2); y1 = csub(a, c2);
            y2 = cadd(b, d2); y3 = csub(b, d2);
            wy2 = y2; wy3 = y3;
        } else {
            float2 w1 = tw[k << (8 - s)];   // e^{-i*pi*k/Nsz}
            float2 w2 = tw[k << (7 - s)];   // e^{-i*pi*k/(2*Nsz)}
            float2 wc = cmul(w1, c2);
            float2 wd = cmul(w1, d2);
            y0 = cadd(a, wc); y1 = csub(a, wc);
            y2 = cadd(b, wd); y3 = csub(b, wd);
            wy2 = cmul(w2, y2);
            wy3 = cmul(w2, y3);
        }
        float2 my3 = make_float2(wy3.y, -wy3.x);  // -i * wy3

        int d = ((u >> s) << (s + 2)) + k;
        dst[d]           = cadd(y0, wy2);
        dst[d + Nsz]     = cadd(y1, my3);
        dst[d + 2 * Nsz] = csub(y0, wy2);
        dst[d + 3 * Nsz] = csub(y1, my3);
        __syncthreads();
        float2* tmp = src; src = dst; dst = tmp;
    }
    // 'src' now holds Z[0..255] for this frame

    if (valid) {
        float* orow = out + (size_t)t * OUT_STRIDE;
        emit_bin(src, tw, orow, u);
        emit_bin(src, tw, orow, u + 64);
        emit_bin(src, tw, orow, u + 128);
        emit_bin(src, tw, orow, u + 192);
        if (u == 0) emit_bin(src, tw, orow, 256);
    }
}

// ---------------------------------------------------------------------------
extern "C" void kernel_launch(void* const* d_in, const int* in_sizes, int n_in,
                              void* d_out, int out_size) {
    const float* audio = (const float*)d_in[0];
    float* out = (float*)d_out;
    reduce_pass1<<<512, 256>>>(audio);
    reduce_pass2<<<1, 256>>>();
    stft_kernel<<<(NFRAMES + FPB - 1) / FPB, 256>>>(audio, out);
}